// round 8
// baseline (speedup 1.0000x reference)
#include <cuda_runtime.h>
#include <math.h>
#include <stdint.h>

#define KC 4
#define D  8
#define NTRI 36   // lower-triangular 8x8 element count

#define LOG_2PI 1.8378770664093453f
#define LN2F    0.6931471805599453f

__device__ __forceinline__ float rcp_a(float x)  { float y; asm("rcp.approx.f32 %0, %1;"   : "=f"(y) : "f"(x)); return y; }
__device__ __forceinline__ float rsq_a(float x)  { float y; asm("rsqrt.approx.f32 %0, %1;" : "=f"(y) : "f"(x)); return y; }
__device__ __forceinline__ float lg2_a(float x)  { float y; asm("lg2.approx.f32 %0, %1;"   : "=f"(y) : "f"(x)); return y; }

// ---------------------------------------------------------------------------
// Hot-path params: 0.5 folded in (sL = Linv/sqrt2, nb = -bias/sqrt2), so
// lp = cf + sum_r (sL·x + nb)^2 directly.
// ---------------------------------------------------------------------------
struct HotP {
    float sL[KC][NTRI];    // scaled Linv, lower-tri flattened r*(r+1)/2+c
    float nb[KC][D];       // -bias scaled
    float cf[KC];          // 0.5*D*log(2pi) - half_log_det
    int   active[KC];      // class i participates (indices[i] != 0)
    int   tmask[KC];       // one-hot bit of target component
    int   emask[KC];       // bits {j != i : indices[j] == indices[i]} (usually 0)
};

// Tail/finalize params (unscaled, reference-exact math)
struct TailP {
    float Linv[KC][D][D];
    float bias[KC][D];
    float cfix[KC];
    int   active[KC];
    int   tmask[KC];
    int   wmask[KC];
    int   cnt;
    int   _pad;
};

__device__ HotP   g_h;
__device__ TailP  g_p;
__device__ double g_sum;

// ---------------------------------------------------------------------------
// Kernel 1: setup — one thread per component, approx-MUFU rcp/rsqrt/lg2.
// ---------------------------------------------------------------------------
__global__ void setup_kernel(const float* __restrict__ means,
                             const float* __restrict__ covs,
                             const int*   __restrict__ indices)
{
    const int j = threadIdx.x;
    if (blockIdx.x != 0 || j >= KC) return;

    const float INV_SQRT2 = 0.70710678118654752f;

    float L[D][D], Li[D][D];
    const float* a = covs + j * D * D;
    // Cholesky: cov = L * L^T  (approx rsqrt/rcp; cov eigmin >= 0.5)
    #pragma unroll
    for (int r = 0; r < D; ++r) {
        #pragma unroll
        for (int c = 0; c <= r; ++c) {
            float s = a[r * D + c];
            #pragma unroll
            for (int k = 0; k < c; ++k) s -= L[r][k] * L[c][k];
            if (c == r) L[r][c] = s * rsq_a(s);
            else        L[r][c] = s * rcp_a(L[c][c]);
        }
    }
    // Invert lower-triangular L; half-log-det via lg2
    float hld = 0.0f;
    #pragma unroll
    for (int c = 0; c < D; ++c) {
        Li[c][c] = rcp_a(L[c][c]);
        #pragma unroll
        for (int r = c + 1; r < D; ++r) {
            float s = 0.0f;
            #pragma unroll
            for (int k = c; k < r; ++k) s += L[r][k] * Li[k][c];
            Li[r][c] = -s * rcp_a(L[r][r]);
        }
        hld += lg2_a(L[c][c]);
    }
    hld *= LN2F;

    int t = 0;
    #pragma unroll
    for (int r = 0; r < D; ++r)
        #pragma unroll
        for (int c = 0; c <= r; ++c) {
            g_h.sL[j][t] = Li[r][c] * INV_SQRT2;
            ++t;
        }
    #pragma unroll
    for (int r = 0; r < D; ++r)
        #pragma unroll
        for (int c = 0; c < D; ++c)
            g_p.Linv[j][r][c] = (c <= r) ? Li[r][c] : 0.0f;
    #pragma unroll
    for (int r = 0; r < D; ++r) {
        float s = 0.0f;
        #pragma unroll
        for (int c = 0; c <= r; ++c) s += Li[r][c] * means[j * D + c];
        g_p.bias[j][r] = s;
        g_h.nb[j][r]   = -s * INV_SQRT2;
    }
    float cf = 0.5f * (float)D * LOG_2PI - hld;
    g_p.cfix[j] = cf;
    g_h.cf[j]   = cf;

    if (j == 0) {
        g_sum = 0.0;
        int cnt = 0;
        for (int i = 0; i < KC; ++i) {
            int ci = indices[i];
            int act = (ci != 0);
            g_p.active[i] = act;
            g_h.active[i] = act;
            if (act) cnt++;
            int ti = ci; if (ti < 0) ti = 0; if (ti > KC - 1) ti = KC - 1;
            g_p.tmask[i] = 1 << ti;
            g_h.tmask[i] = 1 << ti;
            int wm = 0, em = 0;
            for (int jj = 0; jj < KC; ++jj) {
                if (indices[jj] != ci) wm |= (1 << jj);
                else if (jj != i)      em |= (1 << jj);
            }
            g_p.wmask[i] = wm;
            g_h.emask[i] = em;
        }
        g_p.cnt = cnt;
    }
}

// ---------------------------------------------------------------------------
// Kernel 2: hot path — byte-identical body to the 63.5us R6 kernel; ONLY
// change: __launch_bounds__(256, 2) caps regs at 128 so 2 blocks (16 warps)
// fit per SM (R7 profile: regs=255 -> occ 12.6%, issue 28% was the binder).
// ---------------------------------------------------------------------------
__global__ void __launch_bounds__(256, 2) lp_kernel(const float* __restrict__ pred, int N)
{
    __shared__ HotP sh;
    {
        const int nw = (int)(sizeof(HotP) / 4);
        const int* src = (const int*)&g_h;
        int* dst = (int*)&sh;
        for (int u = threadIdx.x; u < nw; u += blockDim.x) dst[u] = src[u];
    }
    __syncthreads();

    const int N4 = N >> 2;
    const int tid = blockIdx.x * blockDim.x + threadIdx.x;
    const int stride = gridDim.x * blockDim.x;

    float acc = 0.0f;

    for (int v = tid; v < N4; v += stride) {
        #pragma unroll
        for (int i = 0; i < KC; ++i) {
            if (!sh.active[i]) continue;
            const float4* base = (const float4*)pred + (size_t)i * D * N4;
            float4 x[D];
            #pragma unroll
            for (int dd = 0; dd < D; ++dd)
                x[dd] = base[(size_t)dd * N4 + v];

            float lp[KC][4];
            #pragma unroll
            for (int j = 0; j < KC; ++j) {
                float M0 = sh.cf[j], M1 = M0, M2 = M0, M3 = M0;
                int t = 0;
                #pragma unroll
                for (int r = 0; r < D; ++r) {
                    float nb = sh.nb[j][r];
                    float s0 = nb, s1 = nb, s2 = nb, s3 = nb;
                    #pragma unroll
                    for (int c = 0; c <= r; ++c) {
                        float l = sh.sL[j][t]; ++t;
                        s0 = fmaf(l, x[c].x, s0);
                        s1 = fmaf(l, x[c].y, s1);
                        s2 = fmaf(l, x[c].z, s2);
                        s3 = fmaf(l, x[c].w, s3);
                    }
                    M0 = fmaf(s0, s0, M0);
                    M1 = fmaf(s1, s1, M1);
                    M2 = fmaf(s2, s2, M2);
                    M3 = fmaf(s3, s3, M3);
                }
                lp[j][0] = M0; lp[j][1] = M1; lp[j][2] = M2; lp[j][3] = M3;
            }

            const int tm = sh.tmask[i];
            const int em = sh.emask[i];
            #pragma unroll
            for (int s = 0; s < 4; ++s) {
                float e0 = __expf(lp[0][s]);
                float e1 = __expf(lp[1][s]);
                float e2 = __expf(lp[2][s]);
                float e3 = __expf(lp[3][s]);
                // tot_ll + exp(target) == 1e-8 + sum_all - sum_{j!=i, cj==ci}
                float tot = 1e-8f + ((e0 + e1) + (e2 + e3));
                if (em) {
                    tot -= (em & 1) ? e0 : 0.0f;
                    tot -= (em & 2) ? e1 : 0.0f;
                    tot -= (em & 4) ? e2 : 0.0f;
                    tot -= (em & 8) ? e3 : 0.0f;
                }
                float tll = (tm & 1) ? lp[0][s]
                          : (tm & 2) ? lp[1][s]
                          : (tm & 4) ? lp[2][s] : lp[3][s];
                acc += tll - __logf(tot);
            }
        }
    }

    // fp64 block reduction
    double dacc = (double)acc;
    #pragma unroll
    for (int off = 16; off > 0; off >>= 1)
        dacc += __shfl_down_sync(0xffffffffu, dacc, off);
    __shared__ double wsum[8];
    int lane = threadIdx.x & 31;
    int w = threadIdx.x >> 5;
    if (lane == 0) wsum[w] = dacc;
    __syncthreads();
    if (w == 0) {
        int nwarp = blockDim.x >> 5;
        double b = (lane < nwarp) ? wsum[lane] : 0.0;
        #pragma unroll
        for (int off = 4; off > 0; off >>= 1)
            b += __shfl_down_sync(0xffffffffu, b, off);
        if (lane == 0) atomicAdd(&g_sum, b);
    }
}

// ---------------------------------------------------------------------------
// Kernel 3: tail samples (N%4) + finalize scalar output.
// ---------------------------------------------------------------------------
__global__ void final_kernel(const float* __restrict__ pred, int N,
                             float* __restrict__ out)
{
    if (threadIdx.x != 0 || blockIdx.x != 0) return;
    double s = g_sum;
    const int n0 = (N >> 2) << 2;
    for (int n = n0; n < N; ++n) {
        for (int i = 0; i < KC; ++i) {
            if (!g_p.active[i]) continue;
            const float* base = pred + (size_t)i * D * N;
            float lp[KC];
            for (int j = 0; j < KC; ++j) {
                float M = 0.f;
                for (int r = 0; r < D; ++r) {
                    float sr = -g_p.bias[j][r];
                    for (int c = 0; c <= r; ++c)
                        sr = fmaf(g_p.Linv[j][r][c], base[(size_t)c * N + n], sr);
                    M = fmaf(sr, sr, M);
                }
                lp[j] = fmaf(0.5f, M, g_p.cfix[j]);
            }
            int tm = g_p.tmask[i], wm = g_p.wmask[i];
            float tot = 1e-8f, tll = 0.f, et = 0.f;
            for (int j = 0; j < KC; ++j) {
                if ((wm >> j) & 1) tot += __expf(lp[j]);
                if ((tm >> j) & 1) { tll = lp[j]; et = __expf(lp[j]); }
            }
            s += (double)(tll - __logf(tot + et));
        }
    }
    int cnt = g_p.cnt;
    float res = 0.0f;
    if (cnt > 0 && N > 0)
        res = (float)(-s / ((double)N * (double)cnt));
    out[0] = res;
}

// ---------------------------------------------------------------------------
extern "C" void kernel_launch(void* const* d_in, const int* in_sizes, int n_in,
                              void* d_out, int out_size)
{
    const float* pred    = (const float*)d_in[0];  // (K, d, N)
    const float* means   = (const float*)d_in[1];  // (K, d)
    const float* covs    = (const float*)d_in[2];  // (K, d, d)
    const int*   indices = (const int*)d_in[3];    // (K,)

    const int N = in_sizes[0] / (KC * D);

    setup_kernel<<<1, 32>>>(means, covs, indices);

    const int N4 = N >> 2;
    const int threads = 256;
    int blocks = (N4 + threads - 1) / threads;
    if (blocks < 1) blocks = 1;
    lp_kernel<<<blocks, threads>>>(pred, N);

    final_kernel<<<1, 32>>>(pred, N, (float*)d_out);
}

// round 10
// speedup vs baseline: 3.1243x; 3.1243x over previous
#include <cuda_runtime.h>
#include <math.h>
#include <stdint.h>

#define KC 4
#define D  8
#define NTRI 36   // lower-triangular 8x8 element count

#define LOG_2PI 1.8378770664093453f
#define LN2F    0.6931471805599453f

__device__ __forceinline__ float rcp_a(float x)  { float y; asm("rcp.approx.f32 %0, %1;"   : "=f"(y) : "f"(x)); return y; }
__device__ __forceinline__ float rsq_a(float x)  { float y; asm("rsqrt.approx.f32 %0, %1;" : "=f"(y) : "f"(x)); return y; }
__device__ __forceinline__ float lg2_a(float x)  { float y; asm("lg2.approx.f32 %0, %1;"   : "=f"(y) : "f"(x)); return y; }

// Hot-path params (0.5 folded: sL = Linv/sqrt2, nb = -bias/sqrt2, so
// lp = cf + sum_r (sL·x + nb)^2 directly).
struct HotP {
    float sL[KC][NTRI];
    float nb[KC][D];
    float cf[KC];
    int   active[KC];
    int   tmask[KC];
    int   emask[KC];
};

__device__ double g_sum = 0.0;   // reset by final_kernel each launch

// ---------------------------------------------------------------------------
// Per-thread component prep: Cholesky + triangular inverse + log-det (fp32,
// approx MUFU). Writes scaled params for component j into the given HotP.
// ---------------------------------------------------------------------------
__device__ __forceinline__ void prep_component(HotP* p, int j,
                                               const float* __restrict__ means,
                                               const float* __restrict__ covs)
{
    const float INV_SQRT2 = 0.70710678118654752f;
    float L[D][D], Li[D][D];
    const float* a = covs + j * D * D;
    #pragma unroll
    for (int r = 0; r < D; ++r) {
        #pragma unroll
        for (int c = 0; c <= r; ++c) {
            float s = a[r * D + c];
            #pragma unroll
            for (int k = 0; k < c; ++k) s -= L[r][k] * L[c][k];
            if (c == r) L[r][c] = s * rsq_a(s);
            else        L[r][c] = s * rcp_a(L[c][c]);
        }
    }
    float hld = 0.0f;
    #pragma unroll
    for (int c = 0; c < D; ++c) {
        Li[c][c] = rcp_a(L[c][c]);
        #pragma unroll
        for (int r = c + 1; r < D; ++r) {
            float s = 0.0f;
            #pragma unroll
            for (int k = c; k < r; ++k) s += L[r][k] * Li[k][c];
            Li[r][c] = -s * rcp_a(L[r][r]);
        }
        hld += lg2_a(L[c][c]);
    }
    hld *= LN2F;

    int t = 0;
    #pragma unroll
    for (int r = 0; r < D; ++r)
        #pragma unroll
        for (int c = 0; c <= r; ++c) {
            p->sL[j][t] = Li[r][c] * INV_SQRT2;
            ++t;
        }
    #pragma unroll
    for (int r = 0; r < D; ++r) {
        float s = 0.0f;
        #pragma unroll
        for (int c = 0; c <= r; ++c) s += Li[r][c] * means[j * D + c];
        p->nb[j][r] = -s * INV_SQRT2;
    }
    p->cf[j] = 0.5f * (float)D * LOG_2PI - hld;
}

__device__ __forceinline__ void prep_masks(HotP* p, const int* __restrict__ indices)
{
    for (int i = 0; i < KC; ++i) {
        int ci = indices[i];
        p->active[i] = (ci != 0);
        int ti = ci; if (ti < 0) ti = 0; if (ti > KC - 1) ti = KC - 1;
        p->tmask[i] = 1 << ti;
        int em = 0;
        for (int jj = 0; jj < KC; ++jj)
            if (indices[jj] == ci && jj != i) em |= (1 << jj);
        p->emask[i] = em;
    }
}

// ---------------------------------------------------------------------------
// Hot kernel: per-block inline setup (threads 0-3 -> shared, ~1us paid
// concurrently), then the PROVEN 63.5us R6 body, fp64 block reduce.
// ---------------------------------------------------------------------------
__global__ void __launch_bounds__(256) lp_kernel(const float* __restrict__ pred, int N,
                                                 const float* __restrict__ means,
                                                 const float* __restrict__ covs,
                                                 const int*   __restrict__ indices)
{
    __shared__ HotP sh;
    if (threadIdx.x < KC)
        prep_component(&sh, threadIdx.x, means, covs);
    if (threadIdx.x == 0)
        prep_masks(&sh, indices);
    __syncthreads();

    const int N4 = N >> 2;
    const int tid = blockIdx.x * blockDim.x + threadIdx.x;
    const int stride = gridDim.x * blockDim.x;

    float acc = 0.0f;

    for (int v = tid; v < N4; v += stride) {
        #pragma unroll
        for (int i = 0; i < KC; ++i) {
            if (!sh.active[i]) continue;
            const float4* base = (const float4*)pred + (size_t)i * D * N4;
            float4 x[D];
            #pragma unroll
            for (int dd = 0; dd < D; ++dd)
                x[dd] = base[(size_t)dd * N4 + v];

            float lp[KC][4];
            #pragma unroll
            for (int j = 0; j < KC; ++j) {
                float M0 = sh.cf[j], M1 = M0, M2 = M0, M3 = M0;
                int t = 0;
                #pragma unroll
                for (int r = 0; r < D; ++r) {
                    float nb = sh.nb[j][r];
                    float s0 = nb, s1 = nb, s2 = nb, s3 = nb;
                    #pragma unroll
                    for (int c = 0; c <= r; ++c) {
                        float l = sh.sL[j][t]; ++t;
                        s0 = fmaf(l, x[c].x, s0);
                        s1 = fmaf(l, x[c].y, s1);
                        s2 = fmaf(l, x[c].z, s2);
                        s3 = fmaf(l, x[c].w, s3);
                    }
                    M0 = fmaf(s0, s0, M0);
                    M1 = fmaf(s1, s1, M1);
                    M2 = fmaf(s2, s2, M2);
                    M3 = fmaf(s3, s3, M3);
                }
                lp[j][0] = M0; lp[j][1] = M1; lp[j][2] = M2; lp[j][3] = M3;
            }

            const int tm = sh.tmask[i];
            const int em = sh.emask[i];
            #pragma unroll
            for (int s = 0; s < 4; ++s) {
                float e0 = __expf(lp[0][s]);
                float e1 = __expf(lp[1][s]);
                float e2 = __expf(lp[2][s]);
                float e3 = __expf(lp[3][s]);
                float tot = 1e-8f + ((e0 + e1) + (e2 + e3));
                if (em) {
                    tot -= (em & 1) ? e0 : 0.0f;
                    tot -= (em & 2) ? e1 : 0.0f;
                    tot -= (em & 4) ? e2 : 0.0f;
                    tot -= (em & 8) ? e3 : 0.0f;
                }
                float tll = (tm & 1) ? lp[0][s]
                          : (tm & 2) ? lp[1][s]
                          : (tm & 4) ? lp[2][s] : lp[3][s];
                acc += tll - __logf(tot);
            }
        }
    }

    // fp64 block reduction
    double dacc = (double)acc;
    #pragma unroll
    for (int off = 16; off > 0; off >>= 1)
        dacc += __shfl_down_sync(0xffffffffu, dacc, off);
    __shared__ double wsum[8];
    int lane = threadIdx.x & 31;
    int w = threadIdx.x >> 5;
    if (lane == 0) wsum[w] = dacc;
    __syncthreads();
    if (w == 0) {
        int nwarp = blockDim.x >> 5;
        double b = (lane < nwarp) ? wsum[lane] : 0.0;
        #pragma unroll
        for (int off = 4; off > 0; off >>= 1)
            b += __shfl_down_sync(0xffffffffu, b, off);
        if (lane == 0) atomicAdd(&g_sum, b);
    }
}

// ---------------------------------------------------------------------------
// Finalize: tail samples (only if N%4 != 0), scalar output, g_sum self-reset.
// ---------------------------------------------------------------------------
__global__ void final_kernel(const float* __restrict__ pred, int N,
                             const float* __restrict__ means,
                             const float* __restrict__ covs,
                             const int*   __restrict__ indices,
                             float* __restrict__ out)
{
    if (threadIdx.x != 0 || blockIdx.x != 0) return;
    double s = g_sum;
    const int n0 = (N >> 2) << 2;

    int cnt = 0;
    for (int i = 0; i < KC; ++i) if (indices[i] != 0) cnt++;

    if (n0 < N) {
        __shared__ HotP hp;
        for (int j = 0; j < KC; ++j) prep_component(&hp, j, means, covs);
        prep_masks(&hp, indices);
        for (int n = n0; n < N; ++n) {
            for (int i = 0; i < KC; ++i) {
                if (!hp.active[i]) continue;
                const float* base = pred + (size_t)i * D * N;
                float lp[KC];
                for (int j = 0; j < KC; ++j) {
                    float M = hp.cf[j];
                    int t = 0;
                    for (int r = 0; r < D; ++r) {
                        float sr = hp.nb[j][r];
                        for (int c = 0; c <= r; ++c) {
                            sr = fmaf(hp.sL[j][t], base[(size_t)c * N + n], sr);
                            ++t;
                        }
                        M = fmaf(sr, sr, M);
                    }
                    lp[j] = M;
                }
                int tm = hp.tmask[i], em = hp.emask[i];
                float tot = 1e-8f, tll = 0.f;
                for (int j = 0; j < KC; ++j) {
                    float e = __expf(lp[j]);
                    if (!((em >> j) & 1)) tot += e;
                    if ((tm >> j) & 1) tll = lp[j];
                }
                s += (double)(tll - __logf(tot));
            }
        }
    }

    float res = 0.0f;
    if (cnt > 0 && N > 0)
        res = (float)(-s / ((double)N * (double)cnt));
    out[0] = res;

    g_sum = 0.0;   // reset for next graph replay
    __threadfence();
}

// ---------------------------------------------------------------------------
extern "C" void kernel_launch(void* const* d_in, const int* in_sizes, int n_in,
                              void* d_out, int out_size)
{
    const float* pred    = (const float*)d_in[0];  // (K, d, N)
    const float* means   = (const float*)d_in[1];  // (K, d)
    const float* covs    = (const float*)d_in[2];  // (K, d, d)
    const int*   indices = (const int*)d_in[3];    // (K,)

    const int N = in_sizes[0] / (KC * D);
    const int N4 = N >> 2;

    const int threads = 256;
    int blocks = (N4 + threads - 1) / threads;
    if (blocks > 296) blocks = 296;   // <=2 waves at 1 block/SM: inline setup paid ~twice
    if (blocks < 1) blocks = 1;

    lp_kernel<<<blocks, threads>>>(pred, N, means, covs, indices);
    final_kernel<<<1, 32>>>(pred, N, means, covs, indices, (float*)d_out);
}